// round 4
// baseline (speedup 1.0000x reference)
#include <cuda_runtime.h>
#include <cuda_bf16.h>
#include <math.h>

// ---------------- problem constants ----------------
#define NMAX 10000
#define EMAX 320000
#define MMAX (EMAX + NMAX)   // edges + self loops

// ---------------- device scratch ----------------
__device__ __align__(16) float g_H0 [NMAX * 512];
__device__ __align__(16) float g_H0A[NMAX * 512];
__device__ __align__(16) float g_H1 [NMAX * 128];
__device__ __align__(16) float g_H1A[NMAX * 128];
__device__ __align__(16) float g_H2 [NMAX * 128];
__device__ __align__(16) float g_AS0[NMAX * 4];
__device__ __align__(16) float g_AD0[NMAX * 4];
__device__ __align__(16) float g_AS1[NMAX];
__device__ __align__(16) float g_AD1[NMAX];
__device__ __align__(16) float g_S1 [NMAX];
__device__ __align__(16) float g_S2 [NMAX];
__device__ __align__(16) int   g_deg[NMAX];
__device__ __align__(16) int   g_off[NMAX + 1];
__device__ __align__(16) int   g_cur[NMAX];
__device__ __align__(16) int   g_srt[MMAX];

// buffer ids
#define B_H0   0
#define B_H0A  1
#define B_H1   2
#define B_H1A  3
#define B_H2   4
#define B_AS0  5
#define B_AD0  6
#define B_AS1  7
#define B_AD1  8
#define B_S1   9
#define B_S2   10
#define B_EXT  (-1)

__device__ __forceinline__ float* buf_sel(int id) {
    switch (id) {
        case B_H0:  return g_H0;
        case B_H0A: return g_H0A;
        case B_H1:  return g_H1;
        case B_H1A: return g_H1A;
        case B_H2:  return g_H2;
        case B_AS0: return g_AS0;
        case B_AD0: return g_AD0;
        case B_AS1: return g_AS1;
        case B_AD1: return g_AD1;
        case B_S1:  return g_S1;
        default:    return g_S2;
    }
}

// ---------------- CSR build kernels ----------------
__global__ void zero_deg_kernel(int n) {
    int i = blockIdx.x * blockDim.x + threadIdx.x;
    if (i < n) g_deg[i] = 0;
}

__global__ void hist_kernel(const int* __restrict__ ei, int E, int n) {
    int e = blockIdx.x * blockDim.x + threadIdx.x;
    int M = E + n;
    if (e >= M) return;
    int dst = (e < E) ? ei[E + e] : (e - E);
    if ((unsigned)dst < (unsigned)n)
        atomicAdd(&g_deg[dst], 1);
}

__global__ void scan_kernel(int n) {
    __shared__ int sm[1024];
    int t = threadIdx.x;
    int chunk = (n + 1023) >> 10;
    int b = t * chunk;
    int e = min(n, b + chunk);
    int s = 0;
    for (int i = b; i < e; i++) s += g_deg[i];
    sm[t] = s;
    __syncthreads();
    for (int o = 1; o < 1024; o <<= 1) {
        int v = (t >= o) ? sm[t - o] : 0;
        __syncthreads();
        sm[t] += v;
        __syncthreads();
    }
    int run = sm[t] - s;
    for (int i = b; i < e; i++) {
        g_off[i] = run;
        g_cur[i] = run;
        run += g_deg[i];
    }
    if (t == 1023) g_off[n] = sm[1023];
}

__global__ void scatter_kernel(const int* __restrict__ ei, int E, int n) {
    int e = blockIdx.x * blockDim.x + threadIdx.x;
    int M = E + n;
    if (e >= M) return;
    int src, dst;
    if (e < E) { src = ei[e]; dst = ei[E + e]; }
    else       { src = e - E; dst = e - E; }
    if ((unsigned)dst >= (unsigned)n || (unsigned)src >= (unsigned)n) return;
    int pos = atomicAdd(&g_cur[dst], 1);
    if (pos < MMAX) g_srt[pos] = src;
}

// ---------------- fp32 GEMM v2: C[M,N] = A[M,K] * B[N,K]^T (+bias) ----------------
// 128x64 tile, 256 threads, 8x4 micro-tile per thread. LDS share ~9% of issues.
#define BM 128
#define BN 64
#define BK 16
__global__ void __launch_bounds__(256, 2)
gemm_abt_kernel(const float* __restrict__ Aext, int aid,
                const float* __restrict__ B,
                const float* __restrict__ bias,
                int cid, int M, int N, int K) {
    const float* A = (aid == B_EXT) ? Aext : buf_sel(aid);
    float* C = buf_sel(cid);

    __shared__ float As[BK][BM + 4];
    __shared__ float Bs[BK][BN + 4];

    int tid = threadIdx.x;          // 256
    int lk = tid & 15;              // k slot for loads
    int lr = tid >> 4;              // 0..15
    int tx = tid & 15;              // col group: cols bn + tx*4 .. +3
    int ty = tid >> 4;              // row group: rows bm + ty*8 .. +7
    int bm = blockIdx.y * BM;
    int bn = blockIdx.x * BN;

    float acc[8][4];
#pragma unroll
    for (int i = 0; i < 8; i++)
#pragma unroll
        for (int j = 0; j < 4; j++) acc[i][j] = 0.f;

    for (int k0 = 0; k0 < K; k0 += BK) {
        // fill As: 128 rows x 16 k
#pragma unroll
        for (int i = 0; i < 8; i++) {
            int r = bm + lr + 16 * i;
            As[lk][lr + 16 * i] = (r < M) ? A[(size_t)r * K + k0 + lk] : 0.f;
        }
        // fill Bs: 64 rows x 16 k (N multiple of 64 -> no guard)
#pragma unroll
        for (int i = 0; i < 4; i++) {
            int rb = bn + lr + 16 * i;
            Bs[lk][lr + 16 * i] = B[(size_t)rb * K + k0 + lk];
        }
        __syncthreads();

#pragma unroll
        for (int kk = 0; kk < BK; kk++) {
            float4 a0 = *(const float4*)&As[kk][ty * 8];
            float4 a1 = *(const float4*)&As[kk][ty * 8 + 4];
            float4 b  = *(const float4*)&Bs[kk][tx * 4];
            float av[8] = {a0.x, a0.y, a0.z, a0.w, a1.x, a1.y, a1.z, a1.w};
#pragma unroll
            for (int i = 0; i < 8; i++) {
                acc[i][0] += av[i] * b.x;
                acc[i][1] += av[i] * b.y;
                acc[i][2] += av[i] * b.z;
                acc[i][3] += av[i] * b.w;
            }
        }
        __syncthreads();
    }

    float4 bb = {0.f, 0.f, 0.f, 0.f};
    if (bias) bb = *(const float4*)&bias[bn + tx * 4];
#pragma unroll
    for (int i = 0; i < 8; i++) {
        int row = bm + ty * 8 + i;
        if (row >= M) continue;
        float4 o;
        o.x = acc[i][0] + bb.x;
        o.y = acc[i][1] + bb.y;
        o.z = acc[i][2] + bb.z;
        o.w = acc[i][3] + bb.w;
        *(float4*)&C[(size_t)row * N + bn + tx * 4] = o;
    }
}

// ---------------- attention coefficients ----------------
__global__ void attn_coef_kernel(int hid, const float* __restrict__ atts,
                                 const float* __restrict__ attd,
                                 int osid, int odid, int heads) {
    const float* H = buf_sel(hid);
    float* osrc = buf_sel(osid);
    float* odst = buf_sel(odid);

    int node = blockIdx.x;
    int t = threadIdx.x;            // 128
    int w = t >> 5, lane = t & 31;
    int Ct = heads * 128;
    float ps[4] = {0.f, 0.f, 0.f, 0.f}, pd[4] = {0.f, 0.f, 0.f, 0.f};
    for (int k = 0; k < heads; k++) {
        float h = H[(size_t)node * Ct + k * 128 + t];
        ps[k] = h * atts[k * 128 + t];
        pd[k] = h * attd[k * 128 + t];
    }
#pragma unroll
    for (int o = 16; o; o >>= 1) {
#pragma unroll
        for (int k = 0; k < 4; k++) {
            ps[k] += __shfl_xor_sync(~0u, ps[k], o);
            pd[k] += __shfl_xor_sync(~0u, pd[k], o);
        }
    }
    __shared__ float ss[4][4], sd[4][4];
    if (lane == 0) {
#pragma unroll
        for (int k = 0; k < 4; k++) { ss[w][k] = ps[k]; sd[w][k] = pd[k]; }
    }
    __syncthreads();
    if (t < heads) {
        osrc[node * heads + t] = ss[0][t] + ss[1][t] + ss[2][t] + ss[3][t];
        odst[node * heads + t] = sd[0][t] + sd[1][t] + sd[2][t] + sd[3][t];
    }
}

// ---------------- layer-0 aggregation ----------------
__global__ void agg0_kernel(const float* __restrict__ b0) {
    int node = blockIdx.x;
    int t = threadIdx.x;            // 128
    int w = t >> 5, lane = t & 31;
    int beg = g_off[node], end = g_off[node + 1];

    float adsth = g_AD0[node * 4 + w];

    float m = -1e30f;
    for (int i = beg + lane; i < end; i += 32) {
        int s = g_srt[i];
        float a = g_AS0[s * 4 + w] + adsth;
        a = (a >= 0.f) ? a : 0.2f * a;
        m = fmaxf(m, a);
    }
#pragma unroll
    for (int o = 16; o; o >>= 1) m = fmaxf(m, __shfl_xor_sync(~0u, m, o));
    __shared__ float mx[4];
    if (lane == 0) mx[w] = m;
    __syncthreads();
    float mh = mx[w];

    float4 acc = {0.f, 0.f, 0.f, 0.f};
    float denom = 0.f;
    for (int i = beg; i < end; i++) {
        int s = g_srt[i];
        float a = g_AS0[s * 4 + w] + adsth;
        a = (a >= 0.f) ? a : 0.2f * a;
        float ex = __expf(a - mh);
        denom += ex;
        float4 v = *(const float4*)&g_H0[(size_t)s * 512 + t * 4];
        acc.x += ex * v.x; acc.y += ex * v.y; acc.z += ex * v.z; acc.w += ex * v.w;
    }
    float inv = 1.f / (denom + 1e-16f);
    float4 bb = *(const float4*)&b0[t * 4];
    float4 o4;
    o4.x = acc.x * inv + bb.x;
    o4.y = acc.y * inv + bb.y;
    o4.z = acc.z * inv + bb.z;
    o4.w = acc.w * inv + bb.w;
    o4.x = (o4.x > 0.f) ? o4.x : expm1f(o4.x);
    o4.y = (o4.y > 0.f) ? o4.y : expm1f(o4.y);
    o4.z = (o4.z > 0.f) ? o4.z : expm1f(o4.z);
    o4.w = (o4.w > 0.f) ? o4.w : expm1f(o4.w);
    *(float4*)&g_H0A[(size_t)node * 512 + t * 4] = o4;
}

// ---------------- layer-1 aggregation ----------------
__global__ void agg1_kernel(const float* __restrict__ b1, int n) {
    int w = threadIdx.x >> 5, lane = threadIdx.x & 31;
    int node = blockIdx.x * 4 + w;
    if (node >= n) return;
    int beg = g_off[node], end = g_off[node + 1];
    float adv = g_AD1[node];

    float m = -1e30f;
    for (int i = beg + lane; i < end; i += 32) {
        float a = g_AS1[g_srt[i]] + adv;
        a = (a >= 0.f) ? a : 0.2f * a;
        m = fmaxf(m, a);
    }
#pragma unroll
    for (int o = 16; o; o >>= 1) m = fmaxf(m, __shfl_xor_sync(~0u, m, o));

    float4 acc = {0.f, 0.f, 0.f, 0.f};
    float denom = 0.f;
    for (int i = beg; i < end; i++) {
        int s = g_srt[i];
        float a = g_AS1[s] + adv;
        a = (a >= 0.f) ? a : 0.2f * a;
        float ex = __expf(a - m);
        denom += ex;
        float4 v = *(const float4*)&g_H1[(size_t)s * 128 + lane * 4];
        acc.x += ex * v.x; acc.y += ex * v.y; acc.z += ex * v.z; acc.w += ex * v.w;
    }
    float inv = 1.f / (denom + 1e-16f);
    float4 bb = *(const float4*)&b1[lane * 4];
    float4 o4;
    o4.x = acc.x * inv + bb.x;
    o4.y = acc.y * inv + bb.y;
    o4.z = acc.z * inv + bb.z;
    o4.w = acc.w * inv + bb.w;
    o4.x = (o4.x > 0.f) ? o4.x : expm1f(o4.x);
    o4.y = (o4.y > 0.f) ? o4.y : expm1f(o4.y);
    o4.z = (o4.z > 0.f) ? o4.z : expm1f(o4.z);
    o4.w = (o4.w > 0.f) ? o4.w : expm1f(o4.w);
    *(float4*)&g_H1A[(size_t)node * 128 + lane * 4] = o4;
}

// ---------------- final outer sum ----------------
__global__ void outer_kernel(const float* __restrict__ bedge, float* __restrict__ out, int n) {
    int i = blockIdx.x;
    float v = g_S1[i] + bedge[0];
    float* row = out + (size_t)i * n;
    int n4 = n >> 2;
    const float4* s24 = (const float4*)g_S2;
    for (int j = threadIdx.x; j < n4; j += blockDim.x) {
        float4 b = s24[j];
        float4 o = {v + b.x, v + b.y, v + b.z, v + b.w};
        ((float4*)row)[j] = o;
    }
    for (int j = (n4 << 2) + threadIdx.x; j < n; j += blockDim.x)
        row[j] = v + g_S2[j];
}

// ---------------- host launcher ----------------
extern "C" void kernel_launch(void* const* d_in, const int* in_sizes, int n_in,
                              void* d_out, int out_size) {
    const float* x        = (const float*)d_in[0];
    const int*   ei       = (const int*)d_in[1];     // int32
    const float* W0       = (const float*)d_in[2];
    const float* att_src0 = (const float*)d_in[3];
    const float* att_dst0 = (const float*)d_in[4];
    const float* b0       = (const float*)d_in[5];
    const float* W1       = (const float*)d_in[6];
    const float* att_src1 = (const float*)d_in[7];
    const float* att_dst1 = (const float*)d_in[8];
    const float* b1       = (const float*)d_in[9];
    const float* Wout     = (const float*)d_in[10];
    const float* bout     = (const float*)d_in[11];
    const float* Wedge    = (const float*)d_in[12];
    const float* bedge    = (const float*)d_in[13];
    float* out = (float*)d_out;

    int n = in_sizes[0] / 128;
    int E = in_sizes[1] / 2;
    int M = E + n;

    // ---- CSR build ----
    zero_deg_kernel<<<(n + 255) / 256, 256>>>(n);
    hist_kernel<<<(M + 255) / 256, 256>>>(ei, E, n);
    scan_kernel<<<1, 1024>>>(n);
    scatter_kernel<<<(M + 255) / 256, 256>>>(ei, E, n);

    // ---- layer 0: H0 = x @ W0^T ----
    {
        dim3 grid(512 / BN, (n + BM - 1) / BM);
        gemm_abt_kernel<<<grid, 256>>>(x, B_EXT, W0, nullptr, B_H0, n, 512, 128);
    }
    attn_coef_kernel<<<n, 128>>>(B_H0, att_src0, att_dst0, B_AS0, B_AD0, 4);
    agg0_kernel<<<n, 128>>>(b0);

    // ---- layer 1: H1 = H0A @ W1^T ----
    {
        dim3 grid(128 / BN, (n + BM - 1) / BM);
        gemm_abt_kernel<<<grid, 256>>>(nullptr, B_H0A, W1, nullptr, B_H1, n, 128, 512);
    }
    attn_coef_kernel<<<n, 128>>>(B_H1, att_src1, att_dst1, B_AS1, B_AD1, 1);
    agg1_kernel<<<(n + 3) / 4, 128>>>(b1, n);

    // ---- output projection ----
    {
        dim3 grid(128 / BN, (n + BM - 1) / BM);
        gemm_abt_kernel<<<grid, 256>>>(nullptr, B_H1A, Wout, bout, B_H2, n, 128, 128);
    }

    // ---- edge scores ----
    attn_coef_kernel<<<n, 128>>>(B_H2, Wedge, Wedge + 128, B_S1, B_S2, 1);

    // ---- final n x n outer sum ----
    outer_kernel<<<n, 256>>>(bedge, out, n);
}

// round 5
// speedup vs baseline: 1.1201x; 1.1201x over previous
#include <cuda_runtime.h>
#include <cuda_bf16.h>
#include <math.h>

// ---------------- problem constants ----------------
#define NMAX 10000
#define EMAX 320000
#define MMAX (EMAX + NMAX)   // edges + self loops

// ---------------- device scratch ----------------
__device__ __align__(16) float g_H0 [NMAX * 512];
__device__ __align__(16) float g_H0A[NMAX * 512];
__device__ __align__(16) float g_H1 [NMAX * 128];
__device__ __align__(16) float g_H1A[NMAX * 128];
__device__ __align__(16) float g_H2 [NMAX * 128];
__device__ __align__(16) float g_AS0[NMAX * 4];
__device__ __align__(16) float g_AD0[NMAX * 4];
__device__ __align__(16) float g_AS1[NMAX];
__device__ __align__(16) float g_AD1[NMAX];
__device__ __align__(16) float g_S1 [NMAX];
__device__ __align__(16) float g_S2 [NMAX];
__device__ __align__(16) int   g_deg[NMAX];
__device__ __align__(16) int   g_off[NMAX + 1];
__device__ __align__(16) int   g_cur[NMAX];
__device__ __align__(16) int   g_srt[MMAX];

// buffer ids
#define B_H0   0
#define B_H0A  1
#define B_H1   2
#define B_H1A  3
#define B_H2   4
#define B_AS0  5
#define B_AD0  6
#define B_AS1  7
#define B_AD1  8
#define B_S1   9
#define B_S2   10
#define B_EXT  (-1)

__device__ __forceinline__ float* buf_sel(int id) {
    switch (id) {
        case B_H0:  return g_H0;
        case B_H0A: return g_H0A;
        case B_H1:  return g_H1;
        case B_H1A: return g_H1A;
        case B_H2:  return g_H2;
        case B_AS0: return g_AS0;
        case B_AD0: return g_AD0;
        case B_AS1: return g_AS1;
        case B_AD1: return g_AD1;
        case B_S1:  return g_S1;
        default:    return g_S2;
    }
}

// ---------------- CSR build kernels ----------------
__global__ void zero_deg_kernel(int n) {
    int i = blockIdx.x * blockDim.x + threadIdx.x;
    if (i < n) g_deg[i] = 0;
}

__global__ void hist_kernel(const int* __restrict__ ei, int E, int n) {
    int e = blockIdx.x * blockDim.x + threadIdx.x;
    int M = E + n;
    if (e >= M) return;
    int dst = (e < E) ? ei[E + e] : (e - E);
    if ((unsigned)dst < (unsigned)n)
        atomicAdd(&g_deg[dst], 1);
}

__global__ void scan_kernel(int n) {
    __shared__ int sm[1024];
    int t = threadIdx.x;
    int chunk = (n + 1023) >> 10;
    int b = t * chunk;
    int e = min(n, b + chunk);
    int s = 0;
    for (int i = b; i < e; i++) s += g_deg[i];
    sm[t] = s;
    __syncthreads();
    for (int o = 1; o < 1024; o <<= 1) {
        int v = (t >= o) ? sm[t - o] : 0;
        __syncthreads();
        sm[t] += v;
        __syncthreads();
    }
    int run = sm[t] - s;
    for (int i = b; i < e; i++) {
        g_off[i] = run;
        g_cur[i] = run;
        run += g_deg[i];
    }
    if (t == 1023) g_off[n] = sm[1023];
}

__global__ void scatter_kernel(const int* __restrict__ ei, int E, int n) {
    int e = blockIdx.x * blockDim.x + threadIdx.x;
    int M = E + n;
    if (e >= M) return;
    int src, dst;
    if (e < E) { src = ei[e]; dst = ei[E + e]; }
    else       { src = e - E; dst = e - E; }
    if ((unsigned)dst >= (unsigned)n || (unsigned)src >= (unsigned)n) return;
    int pos = atomicAdd(&g_cur[dst], 1);
    if (pos < MMAX) g_srt[pos] = src;
}

// ---------------- fp32 GEMM (round-3 config): C[M,N] = A[M,K] * B[N,K]^T (+bias) ----------------
#define BM 64
#define BN 64
#define BK 16
__global__ void gemm_abt_kernel(const float* __restrict__ Aext, int aid,
                                const float* __restrict__ B,
                                const float* __restrict__ bias,
                                int cid, int M, int N, int K) {
    const float* A = (aid == B_EXT) ? Aext : buf_sel(aid);
    float* C = buf_sel(cid);

    __shared__ float As[BK][BM + 4];
    __shared__ float Bs[BK][BN + 4];
    int tid = threadIdx.x;          // 256
    int tx = tid & 15;
    int ty = tid >> 4;
    int lk = tid & 15;
    int lr = tid >> 4;
    int bm = blockIdx.y * BM;
    int bn = blockIdx.x * BN;

    float acc[4][4] = {};

    for (int k0 = 0; k0 < K; k0 += BK) {
#pragma unroll
        for (int i = 0; i < 4; i++) {
            int r = bm + lr + 16 * i;
            As[lk][lr + 16 * i] = (r < M) ? A[(size_t)r * K + k0 + lk] : 0.f;
            int rb = bn + lr + 16 * i;
            Bs[lk][lr + 16 * i] = B[(size_t)rb * K + k0 + lk];
        }
        __syncthreads();
#pragma unroll
        for (int kk = 0; kk < BK; kk++) {
            float4 a = *(const float4*)&As[kk][ty * 4];
            float4 b = *(const float4*)&Bs[kk][tx * 4];
            acc[0][0] += a.x * b.x; acc[0][1] += a.x * b.y; acc[0][2] += a.x * b.z; acc[0][3] += a.x * b.w;
            acc[1][0] += a.y * b.x; acc[1][1] += a.y * b.y; acc[1][2] += a.y * b.z; acc[1][3] += a.y * b.w;
            acc[2][0] += a.z * b.x; acc[2][1] += a.z * b.y; acc[2][2] += a.z * b.z; acc[2][3] += a.z * b.w;
            acc[3][0] += a.w * b.x; acc[3][1] += a.w * b.y; acc[3][2] += a.w * b.z; acc[3][3] += a.w * b.w;
        }
        __syncthreads();
    }

#pragma unroll
    for (int i = 0; i < 4; i++) {
        int row = bm + ty * 4 + i;
        if (row >= M) continue;
        int col = bn + tx * 4;
        float4 o;
        o.x = acc[i][0]; o.y = acc[i][1]; o.z = acc[i][2]; o.w = acc[i][3];
        if (bias) {
            o.x += bias[col + 0]; o.y += bias[col + 1];
            o.z += bias[col + 2]; o.w += bias[col + 3];
        }
        *(float4*)&C[(size_t)row * N + col] = o;
    }
}

// ---------------- attention coefficients ----------------
__global__ void attn_coef_kernel(int hid, const float* __restrict__ atts,
                                 const float* __restrict__ attd,
                                 int osid, int odid, int heads) {
    const float* H = buf_sel(hid);
    float* osrc = buf_sel(osid);
    float* odst = buf_sel(odid);

    int node = blockIdx.x;
    int t = threadIdx.x;            // 128
    int w = t >> 5, lane = t & 31;
    int Ct = heads * 128;
    float ps[4] = {0.f, 0.f, 0.f, 0.f}, pd[4] = {0.f, 0.f, 0.f, 0.f};
    for (int k = 0; k < heads; k++) {
        float h = H[(size_t)node * Ct + k * 128 + t];
        ps[k] = h * atts[k * 128 + t];
        pd[k] = h * attd[k * 128 + t];
    }
#pragma unroll
    for (int o = 16; o; o >>= 1) {
#pragma unroll
        for (int k = 0; k < 4; k++) {
            ps[k] += __shfl_xor_sync(~0u, ps[k], o);
            pd[k] += __shfl_xor_sync(~0u, pd[k], o);
        }
    }
    __shared__ float ss[4][4], sd[4][4];
    if (lane == 0) {
#pragma unroll
        for (int k = 0; k < 4; k++) { ss[w][k] = ps[k]; sd[w][k] = pd[k]; }
    }
    __syncthreads();
    if (t < heads) {
        osrc[node * heads + t] = ss[0][t] + ss[1][t] + ss[2][t] + ss[3][t];
        odst[node * heads + t] = sd[0][t] + sd[1][t] + sd[2][t] + sd[3][t];
    }
}

// ---------------- layer-0 aggregation (single pass, no max: softmax shift-invariant,
//                  alpha is O(1) so exp cannot overflow) ----------------
__global__ void agg0_kernel(const float* __restrict__ b0) {
    int node = blockIdx.x;
    int t = threadIdx.x;            // 128
    int w = t >> 5;
    int beg = g_off[node], end = g_off[node + 1];

    float adsth = g_AD0[node * 4 + w];

    float4 acc = {0.f, 0.f, 0.f, 0.f};
    float denom = 0.f;
    for (int i = beg; i < end; i++) {
        int s = g_srt[i];
        float a = g_AS0[s * 4 + w] + adsth;
        a = (a >= 0.f) ? a : 0.2f * a;
        float ex = __expf(a);
        denom += ex;
        float4 v = *(const float4*)&g_H0[(size_t)s * 512 + t * 4];
        acc.x += ex * v.x; acc.y += ex * v.y; acc.z += ex * v.z; acc.w += ex * v.w;
    }
    float inv = 1.f / (denom + 1e-16f);
    float4 bb = *(const float4*)&b0[t * 4];
    float4 o4;
    o4.x = acc.x * inv + bb.x;
    o4.y = acc.y * inv + bb.y;
    o4.z = acc.z * inv + bb.z;
    o4.w = acc.w * inv + bb.w;
    o4.x = (o4.x > 0.f) ? o4.x : expm1f(o4.x);
    o4.y = (o4.y > 0.f) ? o4.y : expm1f(o4.y);
    o4.z = (o4.z > 0.f) ? o4.z : expm1f(o4.z);
    o4.w = (o4.w > 0.f) ? o4.w : expm1f(o4.w);
    *(float4*)&g_H0A[(size_t)node * 512 + t * 4] = o4;
}

// ---------------- layer-1 aggregation (single pass, no max) ----------------
__global__ void agg1_kernel(const float* __restrict__ b1, int n) {
    int w = threadIdx.x >> 5, lane = threadIdx.x & 31;
    int node = blockIdx.x * 4 + w;
    if (node >= n) return;
    int beg = g_off[node], end = g_off[node + 1];
    float adv = g_AD1[node];

    float4 acc = {0.f, 0.f, 0.f, 0.f};
    float denom = 0.f;
    for (int i = beg; i < end; i++) {
        int s = g_srt[i];
        float a = g_AS1[s] + adv;
        a = (a >= 0.f) ? a : 0.2f * a;
        float ex = __expf(a);
        denom += ex;
        float4 v = *(const float4*)&g_H1[(size_t)s * 128 + lane * 4];
        acc.x += ex * v.x; acc.y += ex * v.y; acc.z += ex * v.z; acc.w += ex * v.w;
    }
    float inv = 1.f / (denom + 1e-16f);
    float4 bb = *(const float4*)&b1[lane * 4];
    float4 o4;
    o4.x = acc.x * inv + bb.x;
    o4.y = acc.y * inv + bb.y;
    o4.z = acc.z * inv + bb.z;
    o4.w = acc.w * inv + bb.w;
    o4.x = (o4.x > 0.f) ? o4.x : expm1f(o4.x);
    o4.y = (o4.y > 0.f) ? o4.y : expm1f(o4.y);
    o4.z = (o4.z > 0.f) ? o4.z : expm1f(o4.z);
    o4.w = (o4.w > 0.f) ? o4.w : expm1f(o4.w);
    *(float4*)&g_H1A[(size_t)node * 128 + lane * 4] = o4;
}

// ---------------- final outer sum ----------------
__global__ void outer_kernel(const float* __restrict__ bedge, float* __restrict__ out, int n) {
    int i = blockIdx.x;
    float v = g_S1[i] + bedge[0];
    float* row = out + (size_t)i * n;
    int n4 = n >> 2;
    const float4* s24 = (const float4*)g_S2;
    for (int j = threadIdx.x; j < n4; j += blockDim.x) {
        float4 b = s24[j];
        float4 o = {v + b.x, v + b.y, v + b.z, v + b.w};
        ((float4*)row)[j] = o;
    }
    for (int j = (n4 << 2) + threadIdx.x; j < n; j += blockDim.x)
        row[j] = v + g_S2[j];
}

// ---------------- host launcher ----------------
extern "C" void kernel_launch(void* const* d_in, const int* in_sizes, int n_in,
                              void* d_out, int out_size) {
    const float* x        = (const float*)d_in[0];
    const int*   ei       = (const int*)d_in[1];     // int32
    const float* W0       = (const float*)d_in[2];
    const float* att_src0 = (const float*)d_in[3];
    const float* att_dst0 = (const float*)d_in[4];
    const float* b0       = (const float*)d_in[5];
    const float* W1       = (const float*)d_in[6];
    const float* att_src1 = (const float*)d_in[7];
    const float* att_dst1 = (const float*)d_in[8];
    const float* b1       = (const float*)d_in[9];
    const float* Wout     = (const float*)d_in[10];
    const float* bout     = (const float*)d_in[11];
    const float* Wedge    = (const float*)d_in[12];
    const float* bedge    = (const float*)d_in[13];
    float* out = (float*)d_out;

    int n = in_sizes[0] / 128;
    int E = in_sizes[1] / 2;
    int M = E + n;

    // Fork a side stream so the CSR build (atomic-bound, ~25us) overlaps with
    // GEMM0+attn0 (fma-bound, ~45us). Capture-legal: event-based fork/join.
    // Objects are deliberately not destroyed (kernel_launch runs only a few
    // times; destroying mid-capture would break the graph). No device memory
    // is allocated by these calls.
    cudaStream_t side;
    cudaStreamCreateWithFlags(&side, cudaStreamNonBlocking);
    cudaEvent_t evFork, evJoin;
    cudaEventCreateWithFlags(&evFork, cudaEventDisableTiming);
    cudaEventCreateWithFlags(&evJoin, cudaEventDisableTiming);

    cudaEventRecord(evFork, (cudaStream_t)0);
    cudaStreamWaitEvent(side, evFork, 0);

    // ---- CSR build on side stream ----
    zero_deg_kernel<<<(n + 255) / 256, 256, 0, side>>>(n);
    hist_kernel<<<(M + 255) / 256, 256, 0, side>>>(ei, E, n);
    scan_kernel<<<1, 1024, 0, side>>>(n);
    scatter_kernel<<<(M + 255) / 256, 256, 0, side>>>(ei, E, n);
    cudaEventRecord(evJoin, side);

    // ---- layer 0 GEMM + attn on main stream (independent of CSR) ----
    {
        dim3 grid(512 / BN, (n + BM - 1) / BM);
        gemm_abt_kernel<<<grid, 256>>>(x, B_EXT, W0, nullptr, B_H0, n, 512, 128);
    }
    attn_coef_kernel<<<n, 128>>>(B_H0, att_src0, att_dst0, B_AS0, B_AD0, 4);

    // join: agg0 needs both CSR and attn outputs
    cudaStreamWaitEvent((cudaStream_t)0, evJoin, 0);
    agg0_kernel<<<n, 128>>>(b0);

    // ---- layer 1 ----
    {
        dim3 grid(128 / BN, (n + BM - 1) / BM);
        gemm_abt_kernel<<<grid, 256>>>(nullptr, B_H0A, W1, nullptr, B_H1, n, 128, 512);
    }
    attn_coef_kernel<<<n, 128>>>(B_H1, att_src1, att_dst1, B_AS1, B_AD1, 1);
    agg1_kernel<<<(n + 3) / 4, 128>>>(b1, n);

    // ---- output projection ----
    {
        dim3 grid(128 / BN, (n + BM - 1) / BM);
        gemm_abt_kernel<<<grid, 256>>>(nullptr, B_H1A, Wout, bout, B_H2, n, 128, 128);
    }

    // ---- edge scores ----
    attn_coef_kernel<<<n, 128>>>(B_H2, Wedge, Wedge + 128, B_S1, B_S2, 1);

    // ---- final n x n outer sum ----
    outer_kernel<<<n, 256>>>(bedge, out, n);
}

// round 6
// speedup vs baseline: 1.3872x; 1.2384x over previous
#include <cuda_runtime.h>
#include <cuda_bf16.h>
#include <math.h>

// ---------------- problem constants ----------------
#define NMAX 10000
#define EMAX 320000
#define MMAX (EMAX + NMAX)   // edges + self loops

// ---------------- device scratch ----------------
__device__ __align__(16) float g_H0 [NMAX * 512];
__device__ __align__(16) float g_H0A[NMAX * 512];
__device__ __align__(16) float g_H1 [NMAX * 128];
__device__ __align__(16) float g_H1A[NMAX * 128];
__device__ __align__(16) float g_H2 [NMAX * 128];
__device__ __align__(16) float g_AS0[NMAX * 4];
__device__ __align__(16) float g_AD0[NMAX * 4];
__device__ __align__(16) float g_AS1[NMAX];
__device__ __align__(16) float g_AD1[NMAX];
__device__ __align__(16) float g_S1 [NMAX];
__device__ __align__(16) float g_S2 [NMAX];
__device__ __align__(16) int   g_deg[NMAX];
__device__ __align__(16) int   g_off[NMAX + 1];
__device__ __align__(16) int   g_cur[NMAX];
__device__ __align__(16) int   g_srt[MMAX];

// buffer ids
#define B_H0   0
#define B_H0A  1
#define B_H1   2
#define B_H1A  3
#define B_H2   4
#define B_AS0  5
#define B_AD0  6
#define B_AS1  7
#define B_AD1  8
#define B_S1   9
#define B_S2   10
#define B_EXT  (-1)

__device__ __forceinline__ float* buf_sel(int id) {
    switch (id) {
        case B_H0:  return g_H0;
        case B_H0A: return g_H0A;
        case B_H1:  return g_H1;
        case B_H1A: return g_H1A;
        case B_H2:  return g_H2;
        case B_AS0: return g_AS0;
        case B_AD0: return g_AD0;
        case B_AS1: return g_AS1;
        case B_AD1: return g_AD1;
        case B_S1:  return g_S1;
        default:    return g_S2;
    }
}

// ---------------- CSR build kernels ----------------
__global__ void zero_deg_kernel(int n) {
    int i = blockIdx.x * blockDim.x + threadIdx.x;
    if (i < n) g_deg[i] = 0;
}

__global__ void hist_kernel(const int* __restrict__ ei, int E, int n) {
    int e = blockIdx.x * blockDim.x + threadIdx.x;
    int M = E + n;
    if (e >= M) return;
    int dst = (e < E) ? ei[E + e] : (e - E);
    if ((unsigned)dst < (unsigned)n)
        atomicAdd(&g_deg[dst], 1);
}

__global__ void scan_kernel(int n) {
    __shared__ int sm[1024];
    int t = threadIdx.x;
    int chunk = (n + 1023) >> 10;
    int b = t * chunk;
    int e = min(n, b + chunk);
    int s = 0;
    for (int i = b; i < e; i++) s += g_deg[i];
    sm[t] = s;
    __syncthreads();
    for (int o = 1; o < 1024; o <<= 1) {
        int v = (t >= o) ? sm[t - o] : 0;
        __syncthreads();
        sm[t] += v;
        __syncthreads();
    }
    int run = sm[t] - s;
    for (int i = b; i < e; i++) {
        g_off[i] = run;
        g_cur[i] = run;
        run += g_deg[i];
    }
    if (t == 1023) g_off[n] = sm[1023];
}

__global__ void scatter_kernel(const int* __restrict__ ei, int E, int n) {
    int e = blockIdx.x * blockDim.x + threadIdx.x;
    int M = E + n;
    if (e >= M) return;
    int src, dst;
    if (e < E) { src = ei[e]; dst = ei[E + e]; }
    else       { src = e - E; dst = e - E; }
    if ((unsigned)dst >= (unsigned)n || (unsigned)src >= (unsigned)n) return;
    int pos = atomicAdd(&g_cur[dst], 1);
    if (pos < MMAX) g_srt[pos] = src;
}

// ---------------- TF32 tensor-core GEMM: C[M,N] = A[M,K] * B[N,K]^T (+bias) ----------------
// Tile 128x64, BK=32, 256 threads = 8 warps (2 m-warps x 4 n-warps).
// Each warp: 4 m16 tiles x 2 n8 tiles of mma.m16n8k8.tf32.
// Smem row stride 36 floats (== 4 mod 32) -> fragment LDS is a perfect bank permutation.
#define TBM 128
#define TBN 64
#define TBK 32
#define SSTR (TBK + 4)   // 36

__device__ __forceinline__ unsigned f2tf32(float f) {
    unsigned u;
    asm("cvt.rna.tf32.f32 %0, %1;" : "=r"(u) : "f"(f));
    return u;
}

__global__ void __launch_bounds__(256)
gemm_tc_kernel(const float* __restrict__ Aext, int aid,
               const float* __restrict__ B,
               const float* __restrict__ bias,
               int cid, int M, int N, int K) {
    const float* A = (aid == B_EXT) ? Aext : buf_sel(aid);
    float* C = buf_sel(cid);

    __shared__ unsigned As[TBM * SSTR];
    __shared__ unsigned Bs[TBN * SSTR];

    int tid = threadIdx.x;
    int warp = tid >> 5, lane = tid & 31;
    int wm = warp >> 2;          // 0..1
    int wn = warp & 3;           // 0..3
    int bm = blockIdx.y * TBM;
    int bn = blockIdx.x * TBN;

    int lr = tid >> 3;           // 0..31 (load row)
    int lc = tid & 7;            // 0..7  (load col group: 4 floats)

    float acc[4][2][4];
#pragma unroll
    for (int mt = 0; mt < 4; mt++)
#pragma unroll
        for (int nt = 0; nt < 2; nt++)
#pragma unroll
            for (int r = 0; r < 4; r++) acc[mt][nt][r] = 0.f;

    int qrow = lane >> 2;        // 0..7
    int qcol = lane & 3;         // 0..3

    for (int k0 = 0; k0 < K; k0 += TBK) {
        // load A tile: 128 rows x 32 k (4 iters of 32 rows)
#pragma unroll
        for (int i = 0; i < 4; i++) {
            int rl = lr + 32 * i;
            int rg = bm + rl;
            float4 v = {0.f, 0.f, 0.f, 0.f};
            if (rg < M) v = *(const float4*)&A[(size_t)rg * K + k0 + lc * 4];
            unsigned* d = &As[rl * SSTR + lc * 4];
            d[0] = f2tf32(v.x); d[1] = f2tf32(v.y);
            d[2] = f2tf32(v.z); d[3] = f2tf32(v.w);
        }
        // load B tile: 64 rows x 32 k (2 iters; N multiple of 64 -> no guard)
#pragma unroll
        for (int i = 0; i < 2; i++) {
            int rl = lr + 32 * i;
            float4 v = *(const float4*)&B[(size_t)(bn + rl) * K + k0 + lc * 4];
            unsigned* d = &Bs[rl * SSTR + lc * 4];
            d[0] = f2tf32(v.x); d[1] = f2tf32(v.y);
            d[2] = f2tf32(v.z); d[3] = f2tf32(v.w);
        }
        __syncthreads();

#pragma unroll
        for (int ks = 0; ks < TBK / 8; ks++) {
            int kb = ks * 8;
            // b fragments: 2 n8 tiles
            unsigned bf[2][2];
#pragma unroll
            for (int nt = 0; nt < 2; nt++) {
                int nn = wn * 16 + nt * 8 + qrow;
                bf[nt][0] = Bs[nn * SSTR + kb + qcol];
                bf[nt][1] = Bs[nn * SSTR + kb + qcol + 4];
            }
#pragma unroll
            for (int mt = 0; mt < 4; mt++) {
                int mm = wm * 64 + mt * 16 + qrow;
                unsigned a0 = As[mm * SSTR + kb + qcol];
                unsigned a1 = As[(mm + 8) * SSTR + kb + qcol];
                unsigned a2 = As[mm * SSTR + kb + qcol + 4];
                unsigned a3 = As[(mm + 8) * SSTR + kb + qcol + 4];
#pragma unroll
                for (int nt = 0; nt < 2; nt++) {
                    asm volatile(
                        "mma.sync.aligned.m16n8k8.row.col.f32.tf32.tf32.f32 "
                        "{%0,%1,%2,%3}, {%4,%5,%6,%7}, {%8,%9}, {%0,%1,%2,%3};"
                        : "+f"(acc[mt][nt][0]), "+f"(acc[mt][nt][1]),
                          "+f"(acc[mt][nt][2]), "+f"(acc[mt][nt][3])
                        : "r"(a0), "r"(a1), "r"(a2), "r"(a3),
                          "r"(bf[nt][0]), "r"(bf[nt][1]));
                }
            }
        }
        __syncthreads();
    }

    // epilogue: c0/c1 at (row, col..col+1), c2/c3 at (row+8, ...)
#pragma unroll
    for (int mt = 0; mt < 4; mt++) {
#pragma unroll
        for (int nt = 0; nt < 2; nt++) {
            int row = bm + wm * 64 + mt * 16 + qrow;
            int col = bn + wn * 16 + nt * 8 + qcol * 2;
            float b0 = 0.f, b1 = 0.f;
            if (bias) { b0 = bias[col]; b1 = bias[col + 1]; }
            if (row < M) {
                float2 o = {acc[mt][nt][0] + b0, acc[mt][nt][1] + b1};
                *(float2*)&C[(size_t)row * N + col] = o;
            }
            if (row + 8 < M) {
                float2 o = {acc[mt][nt][2] + b0, acc[mt][nt][3] + b1};
                *(float2*)&C[(size_t)(row + 8) * N + col] = o;
            }
        }
    }
}

// ---------------- attention coefficients ----------------
__global__ void attn_coef_kernel(int hid, const float* __restrict__ atts,
                                 const float* __restrict__ attd,
                                 int osid, int odid, int heads) {
    const float* H = buf_sel(hid);
    float* osrc = buf_sel(osid);
    float* odst = buf_sel(odid);

    int node = blockIdx.x;
    int t = threadIdx.x;            // 128
    int w = t >> 5, lane = t & 31;
    int Ct = heads * 128;
    float ps[4] = {0.f, 0.f, 0.f, 0.f}, pd[4] = {0.f, 0.f, 0.f, 0.f};
    for (int k = 0; k < heads; k++) {
        float h = H[(size_t)node * Ct + k * 128 + t];
        ps[k] = h * atts[k * 128 + t];
        pd[k] = h * attd[k * 128 + t];
    }
#pragma unroll
    for (int o = 16; o; o >>= 1) {
#pragma unroll
        for (int k = 0; k < 4; k++) {
            ps[k] += __shfl_xor_sync(~0u, ps[k], o);
            pd[k] += __shfl_xor_sync(~0u, pd[k], o);
        }
    }
    __shared__ float ss[4][4], sd[4][4];
    if (lane == 0) {
#pragma unroll
        for (int k = 0; k < 4; k++) { ss[w][k] = ps[k]; sd[w][k] = pd[k]; }
    }
    __syncthreads();
    if (t < heads) {
        osrc[node * heads + t] = ss[0][t] + ss[1][t] + ss[2][t] + ss[3][t];
        odst[node * heads + t] = sd[0][t] + sd[1][t] + sd[2][t] + sd[3][t];
    }
}

// ---------------- layer-0 aggregation (single pass, no max) ----------------
__global__ void agg0_kernel(const float* __restrict__ b0) {
    int node = blockIdx.x;
    int t = threadIdx.x;            // 128
    int w = t >> 5;
    int beg = g_off[node], end = g_off[node + 1];

    float adsth = g_AD0[node * 4 + w];

    float4 acc = {0.f, 0.f, 0.f, 0.f};
    float denom = 0.f;
    for (int i = beg; i < end; i++) {
        int s = g_srt[i];
        float a = g_AS0[s * 4 + w] + adsth;
        a = (a >= 0.f) ? a : 0.2f * a;
        float ex = __expf(a);
        denom += ex;
        float4 v = *(const float4*)&g_H0[(size_t)s * 512 + t * 4];
        acc.x += ex * v.x; acc.y += ex * v.y; acc.z += ex * v.z; acc.w += ex * v.w;
    }
    float inv = 1.f / (denom + 1e-16f);
    float4 bb = *(const float4*)&b0[t * 4];
    float4 o4;
    o4.x = acc.x * inv + bb.x;
    o4.y = acc.y * inv + bb.y;
    o4.z = acc.z * inv + bb.z;
    o4.w = acc.w * inv + bb.w;
    o4.x = (o4.x > 0.f) ? o4.x : expm1f(o4.x);
    o4.y = (o4.y > 0.f) ? o4.y : expm1f(o4.y);
    o4.z = (o4.z > 0.f) ? o4.z : expm1f(o4.z);
    o4.w = (o4.w > 0.f) ? o4.w : expm1f(o4.w);
    *(float4*)&g_H0A[(size_t)node * 512 + t * 4] = o4;
}

// ---------------- layer-1 aggregation (single pass, no max) ----------------
__global__ void agg1_kernel(const float* __restrict__ b1, int n) {
    int w = threadIdx.x >> 5, lane = threadIdx.x & 31;
    int node = blockIdx.x * 4 + w;
    if (node >= n) return;
    int beg = g_off[node], end = g_off[node + 1];
    float adv = g_AD1[node];

    float4 acc = {0.f, 0.f, 0.f, 0.f};
    float denom = 0.f;
    for (int i = beg; i < end; i++) {
        int s = g_srt[i];
        float a = g_AS1[s] + adv;
        a = (a >= 0.f) ? a : 0.2f * a;
        float ex = __expf(a);
        denom += ex;
        float4 v = *(const float4*)&g_H1[(size_t)s * 128 + lane * 4];
        acc.x += ex * v.x; acc.y += ex * v.y; acc.z += ex * v.z; acc.w += ex * v.w;
    }
    float inv = 1.f / (denom + 1e-16f);
    float4 bb = *(const float4*)&b1[lane * 4];
    float4 o4;
    o4.x = acc.x * inv + bb.x;
    o4.y = acc.y * inv + bb.y;
    o4.z = acc.z * inv + bb.z;
    o4.w = acc.w * inv + bb.w;
    o4.x = (o4.x > 0.f) ? o4.x : expm1f(o4.x);
    o4.y = (o4.y > 0.f) ? o4.y : expm1f(o4.y);
    o4.z = (o4.z > 0.f) ? o4.z : expm1f(o4.z);
    o4.w = (o4.w > 0.f) ? o4.w : expm1f(o4.w);
    *(float4*)&g_H1A[(size_t)node * 128 + lane * 4] = o4;
}

// ---------------- final outer sum ----------------
__global__ void outer_kernel(const float* __restrict__ bedge, float* __restrict__ out, int n) {
    int i = blockIdx.x;
    float v = g_S1[i] + bedge[0];
    float* row = out + (size_t)i * n;
    int n4 = n >> 2;
    const float4* s24 = (const float4*)g_S2;
    for (int j = threadIdx.x; j < n4; j += blockDim.x) {
        float4 b = s24[j];
        float4 o = {v + b.x, v + b.y, v + b.z, v + b.w};
        ((float4*)row)[j] = o;
    }
    for (int j = (n4 << 2) + threadIdx.x; j < n; j += blockDim.x)
        row[j] = v + g_S2[j];
}

// ---------------- host launcher ----------------
extern "C" void kernel_launch(void* const* d_in, const int* in_sizes, int n_in,
                              void* d_out, int out_size) {
    const float* x        = (const float*)d_in[0];
    const int*   ei       = (const int*)d_in[1];     // int32
    const float* W0       = (const float*)d_in[2];
    const float* att_src0 = (const float*)d_in[3];
    const float* att_dst0 = (const float*)d_in[4];
    const float* b0       = (const float*)d_in[5];
    const float* W1       = (const float*)d_in[6];
    const float* att_src1 = (const float*)d_in[7];
    const float* att_dst1 = (const float*)d_in[8];
    const float* b1       = (const float*)d_in[9];
    const float* Wout     = (const float*)d_in[10];
    const float* bout     = (const float*)d_in[11];
    const float* Wedge    = (const float*)d_in[12];
    const float* bedge    = (const float*)d_in[13];
    float* out = (float*)d_out;

    int n = in_sizes[0] / 128;
    int E = in_sizes[1] / 2;
    int M = E + n;

    // Fork side stream: CSR build overlaps GEMM0+attn0 (capture-legal fork/join).
    cudaStream_t side;
    cudaStreamCreateWithFlags(&side, cudaStreamNonBlocking);
    cudaEvent_t evFork, evJoin;
    cudaEventCreateWithFlags(&evFork, cudaEventDisableTiming);
    cudaEventCreateWithFlags(&evJoin, cudaEventDisableTiming);

    cudaEventRecord(evFork, (cudaStream_t)0);
    cudaStreamWaitEvent(side, evFork, 0);

    zero_deg_kernel<<<(n + 255) / 256, 256, 0, side>>>(n);
    hist_kernel<<<(M + 255) / 256, 256, 0, side>>>(ei, E, n);
    scan_kernel<<<1, 1024, 0, side>>>(n);
    scatter_kernel<<<(M + 255) / 256, 256, 0, side>>>(ei, E, n);
    cudaEventRecord(evJoin, side);

    // ---- layer 0: H0 = x @ W0^T (tf32 TC) ----
    {
        dim3 grid(512 / TBN, (n + TBM - 1) / TBM);
        gemm_tc_kernel<<<grid, 256>>>(x, B_EXT, W0, nullptr, B_H0, n, 512, 128);
    }
    attn_coef_kernel<<<n, 128>>>(B_H0, att_src0, att_dst0, B_AS0, B_AD0, 4);

    cudaStreamWaitEvent((cudaStream_t)0, evJoin, 0);
    agg0_kernel<<<n, 128>>>(b0);

    // ---- layer 1: H1 = H0A @ W1^T ----
    {
        dim3 grid(128 / TBN, (n + TBM - 1) / TBM);
        gemm_tc_kernel<<<grid, 256>>>(nullptr, B_H0A, W1, nullptr, B_H1, n, 128, 512);
    }
    attn_coef_kernel<<<n, 128>>>(B_H1, att_src1, att_dst1, B_AS1, B_AD1, 1);
    agg1_kernel<<<(n + 3) / 4, 128>>>(b1, n);

    // ---- output projection ----
    {
        dim3 grid(128 / TBN, (n + TBM - 1) / TBM);
        gemm_tc_kernel<<<grid, 256>>>(nullptr, B_H1A, Wout, bout, B_H2, n, 128, 128);
    }

    // ---- edge scores ----
    attn_coef_kernel<<<n, 128>>>(B_H2, Wedge, Wedge + 128, B_S1, B_S2, 1);

    // ---- final n x n outer sum ----
    outer_kernel<<<n, 256>>>(bedge, out, n);
}